// round 3
// baseline (speedup 1.0000x reference)
#include <cuda_runtime.h>
#include <math.h>

#define N_NODES 100000
#define HDIM    64
#define CDIM    16
#define NPB     256   // nodes per block (node kernel)
#define TPB     256   // threads per block (node kernel)
#define PAD     32    // bucket slots per (node,type) segment

// -------- scratch (no allocs allowed -> __device__ globals) --------
__device__ float g_S0[(size_t)N_NODES * HDIM];  // sum of feats over type-true edges per dst
__device__ float g_S1[(size_t)N_NODES * HDIM];  // type-false
__device__ float g_c0[N_NODES];                 // count of type-true edges per dst
__device__ float g_c1[N_NODES];                 // count of type-false
__device__ int   g_cnt[2 * N_NODES];            // per-(dst,type) degree
__device__ int   g_slots[(size_t)2 * N_NODES * PAD];  // bucketed src indices
__device__ int   g_et_is_i32;                   // edge_types dtype flag (1 = int32, 0 = uint8)

// =====================================================================
// Detect edge_types dtype. bool-as-uint8: ~50% of bytes are 1.
// bool-as-int32 (LE): only every 4th byte can be 1 (~12.5%).
// =====================================================================
__global__ void detect_et_kernel(const unsigned char* __restrict__ et, int E)
{
    __shared__ int cnt;
    if (threadIdx.x == 0) cnt = 0;
    __syncthreads();
    int K = 4096 < E ? 4096 : E;
    int local = 0;
    for (int i = threadIdx.x; i < K; i += blockDim.x)
        local += (et[i] != 0);
    atomicAdd(&cnt, local);
    __syncthreads();
    if (threadIdx.x == 0)
        g_et_is_i32 = (cnt < K / 4) ? 1 : 0;
}

// =====================================================================
// Place: bucket src index by (dst, type). Int atomics only; rare
// overflow (>PAD, ~impossible for Poisson(5)) falls back to float atomics.
// =====================================================================
__global__ void __launch_bounds__(256) place_kernel(
    const float* __restrict__ feat,
    const int*   __restrict__ src,
    const int*   __restrict__ dst,
    const void*  __restrict__ et,
    int E)
{
    int e = blockIdx.x * blockDim.x + threadIdx.x;
    if (e >= E) return;

    bool t;
    if (g_et_is_i32) t = __ldg((const int*)et + e) != 0;
    else             t = __ldg((const unsigned char*)et + e) != 0;
    int ti = t ? 0 : 1;                 // 0 -> S0 (W0 branch), 1 -> S1

    int d = __ldg(dst + e);
    int s = __ldg(src + e);
    int seg = d * 2 + ti;
    int slot = atomicAdd(&g_cnt[seg], 1);
    if (slot < PAD) {
        g_slots[(size_t)seg * PAD + slot] = s;
    } else {
        // overflow fallback: direct float4 atomics (S zero-initialized)
        float* S = ti ? g_S1 : g_S0;
        const float4* v = (const float4*)(feat + (size_t)s * HDIM);
        float4* p = (float4*)(S + (size_t)d * HDIM);
        #pragma unroll
        for (int l = 0; l < 16; l++) {
            float4 x = __ldg(v + l);
            atomicAdd(p + l, x);
        }
    }
}

// =====================================================================
// Segment sum: 16 threads per (node,type) segment. Indices loaded as
// int4 (MLP 4); each lane gathers its float4 of the src row and
// accumulates; one plain read-add-store per output float4 (owner
// computes; the read picks up any overflow-fallback atomics).
// =====================================================================
__global__ void __launch_bounds__(256) segsum_kernel(
    const float* __restrict__ feat, int Nn)
{
    int gtid = blockIdx.x * blockDim.x + threadIdx.x;
    int grp = gtid >> 4;
    int l   = gtid & 15;
    if (grp >= 2 * Nn) return;
    int d  = grp >> 1;
    int ti = grp & 1;

    int cnt = g_cnt[grp];
    int m = cnt < PAD ? cnt : PAD;
    const int* sl = g_slots + (size_t)grp * PAD;
    const float4* F = (const float4*)feat;

    float4 acc = make_float4(0.f, 0.f, 0.f, 0.f);
    int i = 0;
    for (; i + 4 <= m; i += 4) {
        int4 s4 = *(const int4*)(sl + i);   // slots contiguous
        float4 a = __ldg(F + (size_t)s4.x * 16 + l);
        float4 b = __ldg(F + (size_t)s4.y * 16 + l);
        float4 c = __ldg(F + (size_t)s4.z * 16 + l);
        float4 e = __ldg(F + (size_t)s4.w * 16 + l);
        acc.x += (a.x + b.x) + (c.x + e.x);
        acc.y += (a.y + b.y) + (c.y + e.y);
        acc.z += (a.z + b.z) + (c.z + e.z);
        acc.w += (a.w + b.w) + (c.w + e.w);
    }
    for (; i < m; i++) {
        int s = sl[i];
        float4 a = __ldg(F + (size_t)s * 16 + l);
        acc.x += a.x; acc.y += a.y; acc.z += a.z; acc.w += a.w;
    }

    float* S = ti ? g_S1 : g_S0;
    float4* p = (float4*)(S + (size_t)d * HDIM) + l;
    float4 cur = *p;   // overflow fallback contributions (usually 0)
    cur.x += acc.x; cur.y += acc.y; cur.z += acc.z; cur.w += acc.w;
    *p = cur;

    if (l == 0) (ti ? g_c1 : g_c0)[d] = (float)cnt;
}

// =====================================================================
// Fused node kernel (unchanged from R2): agg = S0@W0^T + c0*b0 +
// S1@W1^T + c1*b1; GRU(agg, feat); out = h@Wout^T + bout.
// =====================================================================
__device__ __forceinline__ void loadW2(float* sW, const float* __restrict__ A,
                                       const float* __restrict__ B, int row0, int tid)
{
    for (int i = tid; i < 4096; i += TPB) {
        int m = i >> 6, k = i & 63;
        sW[k * 64 + m]        = A[(row0 + m) * 64 + k];
        sW[4096 + k * 64 + m] = B[(row0 + m) * 64 + k];
    }
}

__device__ __forceinline__ float sigmoidf_fast(float x)
{
    return __fdividef(1.0f, 1.0f + __expf(-x));
}

__global__ void __launch_bounds__(TPB, 1) node_kernel(
    const float* __restrict__ feat,
    const float* __restrict__ W0,  const float* __restrict__ b0,
    const float* __restrict__ W1,  const float* __restrict__ b1,
    const float* __restrict__ Wih, const float* __restrict__ Whh,
    const float* __restrict__ bih, const float* __restrict__ bhh,
    const float* __restrict__ Wout,const float* __restrict__ bout,
    float* __restrict__ out, int Nn)
{
    extern __shared__ float smem[];
    float* sF = smem;            // 256*65 = 16640
    float* sX = smem + 16640;    // 16640
    float* sW = smem + 33280;    // 8192
    float* sB = smem + 41472;    // 528

    const int tid  = threadIdx.x;
    const int n0   = blockIdx.x * NPB;
    const int n    = n0 + tid;
    const int trow = tid * 65;

    for (int i = tid; i < 528; i += TPB) {
        float v;
        if (i < 64)       v = b0[i];
        else if (i < 128) v = b1[i - 64];
        else if (i < 320) v = bih[i - 128];
        else if (i < 512) v = bhh[i - 320];
        else              v = bout[i - 512];
        sB[i] = v;
    }
    for (int i = tid; i < NPB * 64; i += TPB) {
        int r = i >> 6, c = i & 63;
        int nn = n0 + r;
        sF[r * 65 + c] = (nn < Nn) ? feat[(size_t)nn * 64 + c] : 0.f;
        sX[r * 65 + c] = (nn < Nn) ? g_S0[(size_t)nn * 64 + c] : 0.f;
    }
    for (int i = tid; i < 4096; i += TPB) {
        int m = i >> 6, k = i & 63;
        sW[k * 64 + m]        = W0[m * 64 + k];
        sW[4096 + k * 64 + m] = W1[m * 64 + k];
    }
    __syncthreads();

    // ---- phase A: agg ----
    float acc[64];
    {
        float c0n = (n < Nn) ? g_c0[n] : 0.f;
        float c1n = (n < Nn) ? g_c1[n] : 0.f;
        #pragma unroll
        for (int m = 0; m < 64; m++) acc[m] = c0n * sB[m] + c1n * sB[64 + m];
    }
    #pragma unroll 4
    for (int k = 0; k < 64; k++) {
        float x = sX[trow + k];
        const float4* w4 = (const float4*)(sW + k * 64);
        #pragma unroll
        for (int m4 = 0; m4 < 16; m4++) {
            float4 w = w4[m4];
            acc[4*m4+0] += x * w.x; acc[4*m4+1] += x * w.y;
            acc[4*m4+2] += x * w.z; acc[4*m4+3] += x * w.w;
        }
    }
    __syncthreads();
    for (int i = tid; i < NPB * 64; i += TPB) {
        int r = i >> 6, c = i & 63;
        int nn = n0 + r;
        sX[r * 65 + c] = (nn < Nn) ? g_S1[(size_t)nn * 64 + c] : 0.f;
    }
    __syncthreads();
    #pragma unroll 4
    for (int k = 0; k < 64; k++) {
        float x = sX[trow + k];
        const float4* w4 = (const float4*)(sW + 4096 + k * 64);
        #pragma unroll
        for (int m4 = 0; m4 < 16; m4++) {
            float4 w = w4[m4];
            acc[4*m4+0] += x * w.x; acc[4*m4+1] += x * w.y;
            acc[4*m4+2] += x * w.z; acc[4*m4+3] += x * w.w;
        }
    }
    __syncthreads();
    #pragma unroll
    for (int m = 0; m < 64; m++) sX[trow + m] = acc[m];

    // ---- r gate ----
    loadW2(sW, Wih, Whh, 0, tid);
    __syncthreads();
    float rg[64];
    #pragma unroll
    for (int m = 0; m < 64; m++) rg[m] = sB[128 + m] + sB[320 + m];
    #pragma unroll 2
    for (int k = 0; k < 64; k++) {
        float ag = sX[trow + k], f = sF[trow + k];
        const float4* wa = (const float4*)(sW + k * 64);
        const float4* wb = (const float4*)(sW + 4096 + k * 64);
        #pragma unroll
        for (int m4 = 0; m4 < 16; m4++) {
            float4 a4 = wa[m4], b4 = wb[m4];
            rg[4*m4+0] += ag * a4.x + f * b4.x;
            rg[4*m4+1] += ag * a4.y + f * b4.y;
            rg[4*m4+2] += ag * a4.z + f * b4.z;
            rg[4*m4+3] += ag * a4.w + f * b4.w;
        }
    }
    #pragma unroll
    for (int m = 0; m < 64; m++) rg[m] = sigmoidf_fast(rg[m]);

    // ---- n gate ----
    __syncthreads();
    loadW2(sW, Wih, Whh, 128, tid);
    __syncthreads();
    float nv[64];
    #pragma unroll
    for (int m = 0; m < 64; m++) nv[m] = sB[256 + m] + rg[m] * sB[448 + m];
    #pragma unroll 2
    for (int k = 0; k < 64; k++) {
        float ag = sX[trow + k], f = sF[trow + k];
        const float4* wa = (const float4*)(sW + k * 64);
        const float4* wb = (const float4*)(sW + 4096 + k * 64);
        #pragma unroll
        for (int m4 = 0; m4 < 16; m4++) {
            float4 a4 = wa[m4], b4 = wb[m4];
            nv[4*m4+0] += ag * a4.x + (f * b4.x) * rg[4*m4+0];
            nv[4*m4+1] += ag * a4.y + (f * b4.y) * rg[4*m4+1];
            nv[4*m4+2] += ag * a4.z + (f * b4.z) * rg[4*m4+2];
            nv[4*m4+3] += ag * a4.w + (f * b4.w) * rg[4*m4+3];
        }
    }
    #pragma unroll
    for (int m = 0; m < 64; m++) nv[m] = tanhf(nv[m]);

    // ---- z gate + h ----
    __syncthreads();
    loadW2(sW, Wih, Whh, 64, tid);
    __syncthreads();
    float zg[64];
    #pragma unroll
    for (int m = 0; m < 64; m++) zg[m] = sB[192 + m] + sB[384 + m];
    #pragma unroll 2
    for (int k = 0; k < 64; k++) {
        float ag = sX[trow + k], f = sF[trow + k];
        const float4* wa = (const float4*)(sW + k * 64);
        const float4* wb = (const float4*)(sW + 4096 + k * 64);
        #pragma unroll
        for (int m4 = 0; m4 < 16; m4++) {
            float4 a4 = wa[m4], b4 = wb[m4];
            zg[4*m4+0] += ag * a4.x + f * b4.x;
            zg[4*m4+1] += ag * a4.y + f * b4.y;
            zg[4*m4+2] += ag * a4.z + f * b4.z;
            zg[4*m4+3] += ag * a4.w + f * b4.w;
        }
    }
    #pragma unroll
    for (int m = 0; m < 64; m++) {
        float z = sigmoidf_fast(zg[m]);
        float h = (1.0f - z) * nv[m] + z * sF[trow + m];
        sX[trow + m] = h;
    }

    // ---- classifier ----
    __syncthreads();
    for (int i = tid; i < 1024; i += TPB) {
        int c = i >> 6, k = i & 63;
        sW[k * 16 + c] = Wout[c * 64 + k];
    }
    __syncthreads();
    float o[16];
    #pragma unroll
    for (int c = 0; c < 16; c++) o[c] = sB[512 + c];
    #pragma unroll 4
    for (int k = 0; k < 64; k++) {
        float hv = sX[trow + k];
        const float4* w = (const float4*)(sW + k * 16);
        #pragma unroll
        for (int c4 = 0; c4 < 4; c4++) {
            float4 ww = w[c4];
            o[4*c4+0] += hv * ww.x; o[4*c4+1] += hv * ww.y;
            o[4*c4+2] += hv * ww.z; o[4*c4+3] += hv * ww.w;
        }
    }
    if (n < Nn) {
        float4* po = (float4*)(out + (size_t)n * 16);
        po[0] = make_float4(o[0],  o[1],  o[2],  o[3]);
        po[1] = make_float4(o[4],  o[5],  o[6],  o[7]);
        po[2] = make_float4(o[8],  o[9],  o[10], o[11]);
        po[3] = make_float4(o[12], o[13], o[14], o[15]);
    }
}

// =====================================================================
extern "C" void kernel_launch(void* const* d_in, const int* in_sizes, int n_in,
                              void* d_out, int out_size)
{
    const float* feat = (const float*)d_in[0];
    const int*   src  = (const int*)d_in[1];
    const int*   dst  = (const int*)d_in[2];
    const void*  et   = d_in[3];
    const float* W0   = (const float*)d_in[4];
    const float* b0   = (const float*)d_in[5];
    const float* W1   = (const float*)d_in[6];
    const float* b1   = (const float*)d_in[7];
    const float* Wih  = (const float*)d_in[8];
    const float* Whh  = (const float*)d_in[9];
    const float* bih  = (const float*)d_in[10];
    const float* bhh  = (const float*)d_in[11];
    const float* Wout = (const float*)d_in[12];
    const float* bout = (const float*)d_in[13];
    float* out = (float*)d_out;

    const int E  = in_sizes[1];
    const int Nn = in_sizes[0] / HDIM;

    void* p;
    cudaGetSymbolAddress(&p, g_S0);
    cudaMemsetAsync(p, 0, sizeof(float) * (size_t)N_NODES * HDIM);
    cudaGetSymbolAddress(&p, g_S1);
    cudaMemsetAsync(p, 0, sizeof(float) * (size_t)N_NODES * HDIM);
    cudaGetSymbolAddress(&p, g_cnt);
    cudaMemsetAsync(p, 0, sizeof(int) * 2 * N_NODES);

    detect_et_kernel<<<1, 256>>>((const unsigned char*)et, E);

    place_kernel<<<(E + 255) / 256, 256>>>(feat, src, dst, et, E);

    {
        long long tot = (long long)(2 * Nn) * 16;
        int blocks = (int)((tot + 255) / 256);
        segsum_kernel<<<blocks, 256>>>(feat, Nn);
    }
    {
        size_t smem = (size_t)(16640 * 2 + 8192 + 528) * sizeof(float); // 168000 B
        cudaFuncSetAttribute(node_kernel, cudaFuncAttributeMaxDynamicSharedMemorySize, (int)smem);
        int nb = (Nn + NPB - 1) / NPB;
        node_kernel<<<nb, TPB, smem>>>(feat, W0, b0, W1, b1, Wih, Whh,
                                       bih, bhh, Wout, bout, out, Nn);
    }
}

// round 4
// speedup vs baseline: 1.1625x; 1.1625x over previous
#include <cuda_runtime.h>
#include <math.h>

#define N_NODES 100000
#define HDIM    64
#define CDIM    16
#define NPB     128   // nodes per block (node kernel)
#define TPB     256   // threads per block (node kernel), 2 threads per node
#define PAD     32    // bucket slots per (node,type) segment
#define WSTR    68    // padded stride (floats) per k-row of weight tile

// -------- scratch (no allocs allowed -> __device__ globals) --------
__device__ float g_S0[(size_t)N_NODES * HDIM];
__device__ float g_S1[(size_t)N_NODES * HDIM];
__device__ float g_c0[N_NODES];
__device__ float g_c1[N_NODES];
__device__ int   g_cnt[2 * N_NODES];
__device__ int   g_slots[(size_t)2 * N_NODES * PAD];
__device__ int   g_et_is_i32;

// =====================================================================
__global__ void detect_et_kernel(const unsigned char* __restrict__ et, int E)
{
    __shared__ int cnt;
    if (threadIdx.x == 0) cnt = 0;
    __syncthreads();
    int K = 4096 < E ? 4096 : E;
    int local = 0;
    for (int i = threadIdx.x; i < K; i += blockDim.x)
        local += (et[i] != 0);
    atomicAdd(&cnt, local);
    __syncthreads();
    if (threadIdx.x == 0)
        g_et_is_i32 = (cnt < K / 4) ? 1 : 0;
}

// =====================================================================
__global__ void __launch_bounds__(256) place_kernel(
    const float* __restrict__ feat,
    const int*   __restrict__ src,
    const int*   __restrict__ dst,
    const void*  __restrict__ et,
    int E)
{
    int e = blockIdx.x * blockDim.x + threadIdx.x;
    if (e >= E) return;

    bool t;
    if (g_et_is_i32) t = __ldg((const int*)et + e) != 0;
    else             t = __ldg((const unsigned char*)et + e) != 0;
    int ti = t ? 0 : 1;

    int d = __ldg(dst + e);
    int s = __ldg(src + e);
    int seg = d * 2 + ti;
    int slot = atomicAdd(&g_cnt[seg], 1);
    if (slot < PAD) {
        g_slots[(size_t)seg * PAD + slot] = s;
    } else {
        float* S = ti ? g_S1 : g_S0;
        const float4* v = (const float4*)(feat + (size_t)s * HDIM);
        float4* p = (float4*)(S + (size_t)d * HDIM);
        #pragma unroll
        for (int l = 0; l < 16; l++) {
            float4 x = __ldg(v + l);
            atomicAdd(p + l, x);
        }
    }
}

// =====================================================================
__global__ void __launch_bounds__(256) segsum_kernel(
    const float* __restrict__ feat, int Nn)
{
    int gtid = blockIdx.x * blockDim.x + threadIdx.x;
    int grp = gtid >> 4;
    int l   = gtid & 15;
    if (grp >= 2 * Nn) return;
    int d  = grp >> 1;
    int ti = grp & 1;

    int cnt = g_cnt[grp];
    int m = cnt < PAD ? cnt : PAD;
    const int* sl = g_slots + (size_t)grp * PAD;
    const float4* F = (const float4*)feat;

    float4 acc = make_float4(0.f, 0.f, 0.f, 0.f);
    int i = 0;
    for (; i + 4 <= m; i += 4) {
        int4 s4 = *(const int4*)(sl + i);
        float4 a = __ldg(F + (size_t)s4.x * 16 + l);
        float4 b = __ldg(F + (size_t)s4.y * 16 + l);
        float4 c = __ldg(F + (size_t)s4.z * 16 + l);
        float4 e = __ldg(F + (size_t)s4.w * 16 + l);
        acc.x += (a.x + b.x) + (c.x + e.x);
        acc.y += (a.y + b.y) + (c.y + e.y);
        acc.z += (a.z + b.z) + (c.z + e.z);
        acc.w += (a.w + b.w) + (c.w + e.w);
    }
    for (; i < m; i++) {
        int s = sl[i];
        float4 a = __ldg(F + (size_t)s * 16 + l);
        acc.x += a.x; acc.y += a.y; acc.z += a.z; acc.w += a.w;
    }

    float* S = ti ? g_S1 : g_S0;
    float4* p = (float4*)(S + (size_t)d * HDIM) + l;
    float4 cur = *p;
    cur.x += acc.x; cur.y += acc.y; cur.z += acc.z; cur.w += acc.w;
    *p = cur;

    if (l == 0) (ti ? g_c1 : g_c0)[d] = (float)cnt;
}

// =====================================================================
// Node kernel v2: 2 threads per node (each owns 32 of 64 outputs),
// NPB=128 nodes/CTA, smem 103KB -> 2 CTAs/SM (25% occ).
// Weight tiles stored k-major with stride 68 (coalesced LDG, ~conflict-
// free STS, 16B-aligned float4 broadcast reads).
// =====================================================================
__device__ __forceinline__ void loadW2(float* sW, const float* __restrict__ A,
                                       const float* __restrict__ B, int row0, int tid)
{
    for (int i = tid; i < 4096; i += TPB) {
        int k = i & 63, m = i >> 6;
        sW[k * WSTR + m]              = A[(row0 + m) * 64 + k];
        sW[64 * WSTR + k * WSTR + m]  = B[(row0 + m) * 64 + k];
    }
}

__device__ __forceinline__ float sigmoidf_fast(float x)
{
    return __fdividef(1.0f, 1.0f + __expf(-x));
}

__global__ void __launch_bounds__(TPB, 2) node_kernel(
    const float* __restrict__ feat,
    const float* __restrict__ W0,  const float* __restrict__ b0,
    const float* __restrict__ W1,  const float* __restrict__ b1,
    const float* __restrict__ Wih, const float* __restrict__ Whh,
    const float* __restrict__ bih, const float* __restrict__ bhh,
    const float* __restrict__ Wout,const float* __restrict__ bout,
    float* __restrict__ out, int Nn)
{
    extern __shared__ float smem[];
    float* sF = smem;                    // 128*65 = 8320
    float* sX = smem + 8320;             // 8320
    float* sW = smem + 16640;            // 2*64*68 = 8704
    float* sB = smem + 25344;            // 528
    // total 25872 floats = 103488 B

    const int tid   = threadIdx.x;
    const int nid   = tid & (NPB - 1);   // node within block
    const int hh    = tid >> 7;          // output half: 0 or 1
    const int mbase = hh * 32;
    const int n0    = blockIdx.x * NPB;
    const int n     = n0 + nid;
    const int trow  = nid * 65;

    // biases: [0:64) b0 | [64:128) b1 | [128:320) bih | [320:512) bhh | [512:528) bout
    for (int i = tid; i < 528; i += TPB) {
        float v;
        if (i < 64)       v = b0[i];
        else if (i < 128) v = b1[i - 64];
        else if (i < 320) v = bih[i - 128];
        else if (i < 512) v = bhh[i - 320];
        else              v = bout[i - 512];
        sB[i] = v;
    }
    // stage feat + S0; load W0|W1
    for (int i = tid; i < NPB * 64; i += TPB) {
        int r = i >> 6, c = i & 63;
        int nn = n0 + r;
        sF[r * 65 + c] = (nn < Nn) ? feat[(size_t)nn * 64 + c] : 0.f;
        sX[r * 65 + c] = (nn < Nn) ? g_S0[(size_t)nn * 64 + c] : 0.f;
    }
    loadW2(sW, W0, W1, 0, tid);
    __syncthreads();

    // ---- phase A: agg (this thread's 32 outputs) ----
    float acc[32];
    {
        float c0n = (n < Nn) ? g_c0[n] : 0.f;
        float c1n = (n < Nn) ? g_c1[n] : 0.f;
        #pragma unroll
        for (int m = 0; m < 32; m++)
            acc[m] = c0n * sB[mbase + m] + c1n * sB[64 + mbase + m];
    }
    #pragma unroll 4
    for (int k = 0; k < 64; k++) {
        float x = sX[trow + k];
        const float4* w4 = (const float4*)(sW + k * WSTR + mbase);
        #pragma unroll
        for (int m4 = 0; m4 < 8; m4++) {
            float4 w = w4[m4];
            acc[4*m4+0] += x * w.x; acc[4*m4+1] += x * w.y;
            acc[4*m4+2] += x * w.z; acc[4*m4+3] += x * w.w;
        }
    }
    __syncthreads();
    for (int i = tid; i < NPB * 64; i += TPB) {
        int r = i >> 6, c = i & 63;
        int nn = n0 + r;
        sX[r * 65 + c] = (nn < Nn) ? g_S1[(size_t)nn * 64 + c] : 0.f;
    }
    __syncthreads();
    #pragma unroll 4
    for (int k = 0; k < 64; k++) {
        float x = sX[trow + k];
        const float4* w4 = (const float4*)(sW + 64 * WSTR + k * WSTR + mbase);
        #pragma unroll
        for (int m4 = 0; m4 < 8; m4++) {
            float4 w = w4[m4];
            acc[4*m4+0] += x * w.x; acc[4*m4+1] += x * w.y;
            acc[4*m4+2] += x * w.z; acc[4*m4+3] += x * w.w;
        }
    }
    __syncthreads();
    // park agg (each thread writes its own 32 slots of its node's row)
    #pragma unroll
    for (int m = 0; m < 32; m++) sX[trow + mbase + m] = acc[m];

    // ---- r gate ----
    loadW2(sW, Wih, Whh, 0, tid);
    __syncthreads();
    float rg[32];
    #pragma unroll
    for (int m = 0; m < 32; m++) rg[m] = sB[128 + mbase + m] + sB[320 + mbase + m];
    #pragma unroll 2
    for (int k = 0; k < 64; k++) {
        float ag = sX[trow + k], f = sF[trow + k];
        const float4* wa = (const float4*)(sW + k * WSTR + mbase);
        const float4* wb = (const float4*)(sW + 64 * WSTR + k * WSTR + mbase);
        #pragma unroll
        for (int m4 = 0; m4 < 8; m4++) {
            float4 a4 = wa[m4], b4 = wb[m4];
            rg[4*m4+0] += ag * a4.x + f * b4.x;
            rg[4*m4+1] += ag * a4.y + f * b4.y;
            rg[4*m4+2] += ag * a4.z + f * b4.z;
            rg[4*m4+3] += ag * a4.w + f * b4.w;
        }
    }
    #pragma unroll
    for (int m = 0; m < 32; m++) rg[m] = sigmoidf_fast(rg[m]);

    // ---- n gate ----
    __syncthreads();
    loadW2(sW, Wih, Whh, 128, tid);
    __syncthreads();
    float nv[32];
    #pragma unroll
    for (int m = 0; m < 32; m++) nv[m] = sB[256 + mbase + m] + rg[m] * sB[448 + mbase + m];
    #pragma unroll 2
    for (int k = 0; k < 64; k++) {
        float ag = sX[trow + k], f = sF[trow + k];
        const float4* wa = (const float4*)(sW + k * WSTR + mbase);
        const float4* wb = (const float4*)(sW + 64 * WSTR + k * WSTR + mbase);
        #pragma unroll
        for (int m4 = 0; m4 < 8; m4++) {
            float4 a4 = wa[m4], b4 = wb[m4];
            nv[4*m4+0] += ag * a4.x + (f * b4.x) * rg[4*m4+0];
            nv[4*m4+1] += ag * a4.y + (f * b4.y) * rg[4*m4+1];
            nv[4*m4+2] += ag * a4.z + (f * b4.z) * rg[4*m4+2];
            nv[4*m4+3] += ag * a4.w + (f * b4.w) * rg[4*m4+3];
        }
    }
    #pragma unroll
    for (int m = 0; m < 32; m++) nv[m] = tanhf(nv[m]);

    // ---- z gate + h ----
    __syncthreads();
    loadW2(sW, Wih, Whh, 64, tid);
    __syncthreads();
    float zg[32];
    #pragma unroll
    for (int m = 0; m < 32; m++) zg[m] = sB[192 + mbase + m] + sB[384 + mbase + m];
    #pragma unroll 2
    for (int k = 0; k < 64; k++) {
        float ag = sX[trow + k], f = sF[trow + k];
        const float4* wa = (const float4*)(sW + k * WSTR + mbase);
        const float4* wb = (const float4*)(sW + 64 * WSTR + k * WSTR + mbase);
        #pragma unroll
        for (int m4 = 0; m4 < 8; m4++) {
            float4 a4 = wa[m4], b4 = wb[m4];
            zg[4*m4+0] += ag * a4.x + f * b4.x;
            zg[4*m4+1] += ag * a4.y + f * b4.y;
            zg[4*m4+2] += ag * a4.z + f * b4.z;
            zg[4*m4+3] += ag * a4.w + f * b4.w;
        }
    }
    __syncthreads();   // everyone done reading agg in sX
    #pragma unroll
    for (int m = 0; m < 32; m++) {
        float z = sigmoidf_fast(zg[m]);
        float h = (1.0f - z) * nv[m] + z * sF[trow + mbase + m];
        sX[trow + mbase + m] = h;
    }

    // ---- classifier (8 outputs per thread) ----
    for (int i = tid; i < 1024; i += TPB) {
        int k = i & 63, c = i >> 6;
        sW[k * 16 + c] = Wout[c * 64 + k];
    }
    __syncthreads();
    float o[8];
    #pragma unroll
    for (int c = 0; c < 8; c++) o[c] = sB[512 + hh * 8 + c];
    #pragma unroll 4
    for (int k = 0; k < 64; k++) {
        float hv = sX[trow + k];
        const float4* w = (const float4*)(sW + k * 16 + hh * 8);
        #pragma unroll
        for (int c4 = 0; c4 < 2; c4++) {
            float4 ww = w[c4];
            o[4*c4+0] += hv * ww.x; o[4*c4+1] += hv * ww.y;
            o[4*c4+2] += hv * ww.z; o[4*c4+3] += hv * ww.w;
        }
    }
    if (n < Nn) {
        float4* po = (float4*)(out + (size_t)n * 16 + hh * 8);
        po[0] = make_float4(o[0], o[1], o[2], o[3]);
        po[1] = make_float4(o[4], o[5], o[6], o[7]);
    }
}

// =====================================================================
extern "C" void kernel_launch(void* const* d_in, const int* in_sizes, int n_in,
                              void* d_out, int out_size)
{
    const float* feat = (const float*)d_in[0];
    const int*   src  = (const int*)d_in[1];
    const int*   dst  = (const int*)d_in[2];
    const void*  et   = d_in[3];
    const float* W0   = (const float*)d_in[4];
    const float* b0   = (const float*)d_in[5];
    const float* W1   = (const float*)d_in[6];
    const float* b1   = (const float*)d_in[7];
    const float* Wih  = (const float*)d_in[8];
    const float* Whh  = (const float*)d_in[9];
    const float* bih  = (const float*)d_in[10];
    const float* bhh  = (const float*)d_in[11];
    const float* Wout = (const float*)d_in[12];
    const float* bout = (const float*)d_in[13];
    float* out = (float*)d_out;

    const int E  = in_sizes[1];
    const int Nn = in_sizes[0] / HDIM;

    void* p;
    cudaGetSymbolAddress(&p, g_S0);
    cudaMemsetAsync(p, 0, sizeof(float) * (size_t)N_NODES * HDIM);
    cudaGetSymbolAddress(&p, g_S1);
    cudaMemsetAsync(p, 0, sizeof(float) * (size_t)N_NODES * HDIM);
    cudaGetSymbolAddress(&p, g_cnt);
    cudaMemsetAsync(p, 0, sizeof(int) * 2 * N_NODES);

    detect_et_kernel<<<1, 256>>>((const unsigned char*)et, E);

    place_kernel<<<(E + 255) / 256, 256>>>(feat, src, dst, et, E);

    {
        long long tot = (long long)(2 * Nn) * 16;
        int blocks = (int)((tot + 255) / 256);
        segsum_kernel<<<blocks, 256>>>(feat, Nn);
    }
    {
        size_t smem = (size_t)(8320 * 2 + 8704 + 528) * sizeof(float); // 103488 B
        cudaFuncSetAttribute(node_kernel, cudaFuncAttributeMaxDynamicSharedMemorySize, (int)smem);
        int nb = (Nn + NPB - 1) / NPB;
        node_kernel<<<nb, TPB, smem>>>(feat, W0, b0, W1, b1, Wih, Whh,
                                       bih, bhh, Wout, bout, out, Nn);
    }
}

// round 5
// speedup vs baseline: 1.3129x; 1.1294x over previous
#include <cuda_runtime.h>
#include <math.h>

#define N_NODES 100000
#define HDIM    64
#define CDIM    16
#define NPB     128   // nodes per block (node kernel)
#define TPB     256   // threads per block (node kernel), 2 threads per node
#define PAD     32    // bucket slots per (node,type) segment
#define WSTR    68    // padded stride (floats) per k-row of weight tile

typedef unsigned long long ull;

// packed f32x2 helpers (sm_103a FFMA2 path — ptxas emits FFMA2 only from PTX f32x2)
#define PK2(d, s)      do { unsigned _u = __float_as_uint(s); \
    asm("mov.b64 %0, {%1, %1};" : "=l"(d) : "r"(_u)); } while (0)
#define UPK2(lo, hi, s) do { unsigned _a, _b; \
    asm("mov.b64 {%0, %1}, %2;" : "=r"(_a), "=r"(_b) : "l"(s)); \
    lo = __uint_as_float(_a); hi = __uint_as_float(_b); } while (0)
#define FMA2(a, w, x)  asm("fma.rn.f32x2 %0, %1, %2, %0;" : "+l"(a) : "l"(w), "l"(x))
#define MUL2(d, a, b)  asm("mul.rn.f32x2 %0, %1, %2;" : "=l"(d) : "l"(a), "l"(b))
#define ADD2(d, a, b)  asm("add.rn.f32x2 %0, %1, %2;" : "=l"(d) : "l"(a), "l"(b))

// -------- scratch (no allocs allowed -> __device__ globals) --------
__device__ float g_S0[(size_t)N_NODES * HDIM];
__device__ float g_S1[(size_t)N_NODES * HDIM];
__device__ float g_c0[N_NODES];
__device__ float g_c1[N_NODES];
__device__ int   g_cnt[2 * N_NODES];
__device__ int   g_slots[(size_t)2 * N_NODES * PAD];
__device__ int   g_et_is_i32;

// =====================================================================
__global__ void detect_et_kernel(const unsigned char* __restrict__ et, int E)
{
    __shared__ int cnt;
    if (threadIdx.x == 0) cnt = 0;
    __syncthreads();
    int K = 4096 < E ? 4096 : E;
    int local = 0;
    for (int i = threadIdx.x; i < K; i += blockDim.x)
        local += (et[i] != 0);
    atomicAdd(&cnt, local);
    __syncthreads();
    if (threadIdx.x == 0)
        g_et_is_i32 = (cnt < K / 4) ? 1 : 0;
}

// =====================================================================
__global__ void __launch_bounds__(256) place_kernel(
    const float* __restrict__ feat,
    const int*   __restrict__ src,
    const int*   __restrict__ dst,
    const void*  __restrict__ et,
    int E)
{
    int e = blockIdx.x * blockDim.x + threadIdx.x;
    if (e >= E) return;

    bool t;
    if (g_et_is_i32) t = __ldg((const int*)et + e) != 0;
    else             t = __ldg((const unsigned char*)et + e) != 0;
    int ti = t ? 0 : 1;

    int d = __ldg(dst + e);
    int s = __ldg(src + e);
    int seg = d * 2 + ti;
    int slot = atomicAdd(&g_cnt[seg], 1);
    if (slot < PAD) {
        g_slots[(size_t)seg * PAD + slot] = s;
    } else {
        float* S = ti ? g_S1 : g_S0;
        const float4* v = (const float4*)(feat + (size_t)s * HDIM);
        float4* p = (float4*)(S + (size_t)d * HDIM);
        #pragma unroll
        for (int l = 0; l < 16; l++) {
            float4 x = __ldg(v + l);
            atomicAdd(p + l, x);
        }
    }
}

// =====================================================================
__global__ void __launch_bounds__(256) segsum_kernel(
    const float* __restrict__ feat, int Nn)
{
    int gtid = blockIdx.x * blockDim.x + threadIdx.x;
    int grp = gtid >> 4;
    int l   = gtid & 15;
    if (grp >= 2 * Nn) return;
    int d  = grp >> 1;
    int ti = grp & 1;

    int cnt = g_cnt[grp];
    int m = cnt < PAD ? cnt : PAD;
    const int* sl = g_slots + (size_t)grp * PAD;
    const float4* F = (const float4*)feat;

    float4 acc = make_float4(0.f, 0.f, 0.f, 0.f);
    int i = 0;
    for (; i + 4 <= m; i += 4) {
        int4 s4 = *(const int4*)(sl + i);
        float4 a = __ldg(F + (size_t)s4.x * 16 + l);
        float4 b = __ldg(F + (size_t)s4.y * 16 + l);
        float4 c = __ldg(F + (size_t)s4.z * 16 + l);
        float4 e = __ldg(F + (size_t)s4.w * 16 + l);
        acc.x += (a.x + b.x) + (c.x + e.x);
        acc.y += (a.y + b.y) + (c.y + e.y);
        acc.z += (a.z + b.z) + (c.z + e.z);
        acc.w += (a.w + b.w) + (c.w + e.w);
    }
    for (; i < m; i++) {
        int s = sl[i];
        float4 a = __ldg(F + (size_t)s * 16 + l);
        acc.x += a.x; acc.y += a.y; acc.z += a.z; acc.w += a.w;
    }

    float* S = ti ? g_S1 : g_S0;
    float4* p = (float4*)(S + (size_t)d * HDIM) + l;
    float4 cur = *p;
    cur.x += acc.x; cur.y += acc.y; cur.z += acc.z; cur.w += acc.w;
    *p = cur;

    if (l == 0) (ti ? g_c1 : g_c0)[d] = (float)cnt;
}

// =====================================================================
// Node kernel v3: same structure as v2 (2 threads/node, 128 nodes/CTA,
// 2 CTAs/SM) but all gate/agg inner loops use packed fma.rn.f32x2
// (FFMA2) -> half the fma instruction stream.
// =====================================================================
__device__ __forceinline__ void loadW2(float* sW, const float* __restrict__ A,
                                       const float* __restrict__ B, int row0, int tid)
{
    for (int i = tid; i < 4096; i += TPB) {
        int k = i & 63, m = i >> 6;
        sW[k * WSTR + m]              = A[(row0 + m) * 64 + k];
        sW[64 * WSTR + k * WSTR + m]  = B[(row0 + m) * 64 + k];
    }
}

__device__ __forceinline__ float sigmoidf_fast(float x)
{
    return __fdividef(1.0f, 1.0f + __expf(-x));
}

__global__ void __launch_bounds__(TPB, 2) node_kernel(
    const float* __restrict__ feat,
    const float* __restrict__ W0,  const float* __restrict__ b0,
    const float* __restrict__ W1,  const float* __restrict__ b1,
    const float* __restrict__ Wih, const float* __restrict__ Whh,
    const float* __restrict__ bih, const float* __restrict__ bhh,
    const float* __restrict__ Wout,const float* __restrict__ bout,
    float* __restrict__ out, int Nn)
{
    extern __shared__ float smem[];
    float* sF = smem;                    // 128*65 = 8320
    float* sX = smem + 8320;             // 8320
    float* sW = smem + 16640;            // 2*64*68 = 8704
    float* sB = smem + 25344;            // 528

    const int tid   = threadIdx.x;
    const int nid   = tid & (NPB - 1);
    const int hh    = tid >> 7;
    const int mbase = hh * 32;
    const int n0    = blockIdx.x * NPB;
    const int n     = n0 + nid;
    const int trow  = nid * 65;

    for (int i = tid; i < 528; i += TPB) {
        float v;
        if (i < 64)       v = b0[i];
        else if (i < 128) v = b1[i - 64];
        else if (i < 320) v = bih[i - 128];
        else if (i < 512) v = bhh[i - 320];
        else              v = bout[i - 512];
        sB[i] = v;
    }
    for (int i = tid; i < NPB * 64; i += TPB) {
        int r = i >> 6, c = i & 63;
        int nn = n0 + r;
        sF[r * 65 + c] = (nn < Nn) ? feat[(size_t)nn * 64 + c] : 0.f;
        sX[r * 65 + c] = (nn < Nn) ? g_S0[(size_t)nn * 64 + c] : 0.f;
    }
    loadW2(sW, W0, W1, 0, tid);
    __syncthreads();

    // ---- phase A: agg (packed, 16 f32x2 accumulators) ----
    ull acc2[16];
    {
        float c0n = (n < Nn) ? g_c0[n] : 0.f;
        float c1n = (n < Nn) ? g_c1[n] : 0.f;
        ull c02, c12; PK2(c02, c0n); PK2(c12, c1n);
        const ull* pb0 = (const ull*)(sB + mbase);
        const ull* pb1 = (const ull*)(sB + 64 + mbase);
        #pragma unroll
        for (int q = 0; q < 16; q++) {
            MUL2(acc2[q], c02, pb0[q]);
            FMA2(acc2[q], c12, pb1[q]);
        }
    }
    #pragma unroll 4
    for (int k = 0; k < 64; k++) {
        ull x2; PK2(x2, sX[trow + k]);
        const ulonglong2* w2 = (const ulonglong2*)(sW + k * WSTR + mbase);
        #pragma unroll
        for (int q = 0; q < 8; q++) {
            ulonglong2 w = w2[q];
            FMA2(acc2[2*q],   w.x, x2);
            FMA2(acc2[2*q+1], w.y, x2);
        }
    }
    __syncthreads();
    for (int i = tid; i < NPB * 64; i += TPB) {
        int r = i >> 6, c = i & 63;
        int nn = n0 + r;
        sX[r * 65 + c] = (nn < Nn) ? g_S1[(size_t)nn * 64 + c] : 0.f;
    }
    __syncthreads();
    #pragma unroll 4
    for (int k = 0; k < 64; k++) {
        ull x2; PK2(x2, sX[trow + k]);
        const ulonglong2* w2 = (const ulonglong2*)(sW + 64 * WSTR + k * WSTR + mbase);
        #pragma unroll
        for (int q = 0; q < 8; q++) {
            ulonglong2 w = w2[q];
            FMA2(acc2[2*q],   w.x, x2);
            FMA2(acc2[2*q+1], w.y, x2);
        }
    }
    __syncthreads();
    // park agg in own half-row of sX
    #pragma unroll
    for (int q = 0; q < 16; q++) {
        float lo, hi; UPK2(lo, hi, acc2[q]);
        sX[trow + mbase + 2*q]     = lo;
        sX[trow + mbase + 2*q + 1] = hi;
    }

    // ---- r gate ----
    loadW2(sW, Wih, Whh, 0, tid);
    __syncthreads();
    ull rg2[16];
    {
        const ull* pbi = (const ull*)(sB + 128 + mbase);
        const ull* pbh = (const ull*)(sB + 320 + mbase);
        #pragma unroll
        for (int q = 0; q < 16; q++) ADD2(rg2[q], pbi[q], pbh[q]);
    }
    #pragma unroll 4
    for (int k = 0; k < 64; k++) {
        ull ag2, f2;
        PK2(ag2, sX[trow + k]);
        PK2(f2,  sF[trow + k]);
        const ulonglong2* wa = (const ulonglong2*)(sW + k * WSTR + mbase);
        const ulonglong2* wb = (const ulonglong2*)(sW + 64 * WSTR + k * WSTR + mbase);
        #pragma unroll
        for (int q = 0; q < 8; q++) {
            ulonglong2 a = wa[q], b = wb[q];
            FMA2(rg2[2*q],   a.x, ag2);
            FMA2(rg2[2*q],   b.x, f2);
            FMA2(rg2[2*q+1], a.y, ag2);
            FMA2(rg2[2*q+1], b.y, f2);
        }
    }
    #pragma unroll
    for (int q = 0; q < 16; q++) {
        float lo, hi; UPK2(lo, hi, rg2[q]);
        lo = sigmoidf_fast(lo); hi = sigmoidf_fast(hi);
        unsigned a = __float_as_uint(lo), b = __float_as_uint(hi);
        asm("mov.b64 %0, {%1, %2};" : "=l"(rg2[q]) : "r"(a), "r"(b));
    }

    // ---- n gate: nv = i_n + r * h_n ----
    __syncthreads();
    loadW2(sW, Wih, Whh, 128, tid);
    __syncthreads();
    ull nv2[16];
    {
        const ull* pbi = (const ull*)(sB + 256 + mbase);
        const ull* pbh = (const ull*)(sB + 448 + mbase);
        #pragma unroll
        for (int q = 0; q < 16; q++) {
            nv2[q] = pbi[q];
            FMA2(nv2[q], rg2[q], pbh[q]);
        }
    }
    #pragma unroll 4
    for (int k = 0; k < 64; k++) {
        ull ag2, f2;
        PK2(ag2, sX[trow + k]);
        PK2(f2,  sF[trow + k]);
        const ulonglong2* wa = (const ulonglong2*)(sW + k * WSTR + mbase);
        const ulonglong2* wb = (const ulonglong2*)(sW + 64 * WSTR + k * WSTR + mbase);
        #pragma unroll
        for (int q = 0; q < 8; q++) {
            ulonglong2 a = wa[q], b = wb[q];
            ull t0, t1;
            MUL2(t0, b.x, f2);
            MUL2(t1, b.y, f2);
            FMA2(nv2[2*q],   a.x, ag2);
            FMA2(nv2[2*q],   t0, rg2[2*q]);
            FMA2(nv2[2*q+1], a.y, ag2);
            FMA2(nv2[2*q+1], t1, rg2[2*q+1]);
        }
    }
    #pragma unroll
    for (int q = 0; q < 16; q++) {
        float lo, hi; UPK2(lo, hi, nv2[q]);
        lo = tanhf(lo); hi = tanhf(hi);
        unsigned a = __float_as_uint(lo), b = __float_as_uint(hi);
        asm("mov.b64 %0, {%1, %2};" : "=l"(nv2[q]) : "r"(a), "r"(b));
    }

    // ---- z gate + h ----
    __syncthreads();
    loadW2(sW, Wih, Whh, 64, tid);
    __syncthreads();
    ull zg2[16];
    {
        const ull* pbi = (const ull*)(sB + 192 + mbase);
        const ull* pbh = (const ull*)(sB + 384 + mbase);
        #pragma unroll
        for (int q = 0; q < 16; q++) ADD2(zg2[q], pbi[q], pbh[q]);
    }
    #pragma unroll 4
    for (int k = 0; k < 64; k++) {
        ull ag2, f2;
        PK2(ag2, sX[trow + k]);
        PK2(f2,  sF[trow + k]);
        const ulonglong2* wa = (const ulonglong2*)(sW + k * WSTR + mbase);
        const ulonglong2* wb = (const ulonglong2*)(sW + 64 * WSTR + k * WSTR + mbase);
        #pragma unroll
        for (int q = 0; q < 8; q++) {
            ulonglong2 a = wa[q], b = wb[q];
            FMA2(zg2[2*q],   a.x, ag2);
            FMA2(zg2[2*q],   b.x, f2);
            FMA2(zg2[2*q+1], a.y, ag2);
            FMA2(zg2[2*q+1], b.y, f2);
        }
    }
    __syncthreads();   // everyone done reading agg in sX
    #pragma unroll
    for (int q = 0; q < 16; q++) {
        float zlo, zhi, nlo, nhi;
        UPK2(zlo, zhi, zg2[q]);
        UPK2(nlo, nhi, nv2[q]);
        zlo = sigmoidf_fast(zlo); zhi = sigmoidf_fast(zhi);
        float f0 = sF[trow + mbase + 2*q];
        float f1 = sF[trow + mbase + 2*q + 1];
        sX[trow + mbase + 2*q]     = (1.0f - zlo) * nlo + zlo * f0;
        sX[trow + mbase + 2*q + 1] = (1.0f - zhi) * nhi + zhi * f1;
    }

    // ---- classifier (8 outputs per thread) ----
    for (int i = tid; i < 1024; i += TPB) {
        int k = i & 63, c = i >> 6;
        sW[k * 16 + c] = Wout[c * 64 + k];
    }
    __syncthreads();
    float o[8];
    #pragma unroll
    for (int c = 0; c < 8; c++) o[c] = sB[512 + hh * 8 + c];
    #pragma unroll 4
    for (int k = 0; k < 64; k++) {
        float hv = sX[trow + k];
        const float4* w = (const float4*)(sW + k * 16 + hh * 8);
        #pragma unroll
        for (int c4 = 0; c4 < 2; c4++) {
            float4 ww = w[c4];
            o[4*c4+0] += hv * ww.x; o[4*c4+1] += hv * ww.y;
            o[4*c4+2] += hv * ww.z; o[4*c4+3] += hv * ww.w;
        }
    }
    if (n < Nn) {
        float4* po = (float4*)(out + (size_t)n * 16 + hh * 8);
        po[0] = make_float4(o[0], o[1], o[2], o[3]);
        po[1] = make_float4(o[4], o[5], o[6], o[7]);
    }
}

// =====================================================================
extern "C" void kernel_launch(void* const* d_in, const int* in_sizes, int n_in,
                              void* d_out, int out_size)
{
    const float* feat = (const float*)d_in[0];
    const int*   src  = (const int*)d_in[1];
    const int*   dst  = (const int*)d_in[2];
    const void*  et   = d_in[3];
    const float* W0   = (const float*)d_in[4];
    const float* b0   = (const float*)d_in[5];
    const float* W1   = (const float*)d_in[6];
    const float* b1   = (const float*)d_in[7];
    const float* Wih  = (const float*)d_in[8];
    const float* Whh  = (const float*)d_in[9];
    const float* bih  = (const float*)d_in[10];
    const float* bhh  = (const float*)d_in[11];
    const float* Wout = (const float*)d_in[12];
    const float* bout = (const float*)d_in[13];
    float* out = (float*)d_out;

    const int E  = in_sizes[1];
    const int Nn = in_sizes[0] / HDIM;

    void* p;
    cudaGetSymbolAddress(&p, g_S0);
    cudaMemsetAsync(p, 0, sizeof(float) * (size_t)N_NODES * HDIM);
    cudaGetSymbolAddress(&p, g_S1);
    cudaMemsetAsync(p, 0, sizeof(float) * (size_t)N_NODES * HDIM);
    cudaGetSymbolAddress(&p, g_cnt);
    cudaMemsetAsync(p, 0, sizeof(int) * 2 * N_NODES);

    detect_et_kernel<<<1, 256>>>((const unsigned char*)et, E);

    place_kernel<<<(E + 255) / 256, 256>>>(feat, src, dst, et, E);

    {
        long long tot = (long long)(2 * Nn) * 16;
        int blocks = (int)((tot + 255) / 256);
        segsum_kernel<<<blocks, 256>>>(feat, Nn);
    }
    {
        size_t smem = (size_t)(8320 * 2 + 8704 + 528) * sizeof(float); // 103488 B
        cudaFuncSetAttribute(node_kernel, cudaFuncAttributeMaxDynamicSharedMemorySize, (int)smem);
        int nb = (Nn + NPB - 1) / NPB;
        node_kernel<<<nb, TPB, smem>>>(feat, W0, b0, W1, b1, Wih, Whh,
                                       bih, bhh, Wout, bout, out, Nn);
    }
}

// round 6
// speedup vs baseline: 1.7507x; 1.3335x over previous
#include <cuda_runtime.h>
#include <math.h>

#define N_NODES 100000
#define HDIM    64
#define CDIM    16
#define NPB     128   // nodes per block (node kernel)
#define TPB     256   // threads per block: 4 threads per node-pair slot
#define PAD     32    // bucket slots per (node,type) segment
#define WSTR    68    // padded stride (floats) per k-row of weight tile
#define OVF_CAP 65536

typedef unsigned long long ull;

// packed f32x2 helpers (sm_103a FFMA2 path)
#define PK2(d, s)      do { unsigned _u = __float_as_uint(s); \
    asm("mov.b64 %0, {%1, %1};" : "=l"(d) : "r"(_u)); } while (0)
#define UPK2(lo, hi, s) do { unsigned _a, _b; \
    asm("mov.b64 {%0, %1}, %2;" : "=r"(_a), "=r"(_b) : "l"(s)); \
    lo = __uint_as_float(_a); hi = __uint_as_float(_b); } while (0)
#define RPK2(d, a, b)  do { unsigned _a = __float_as_uint(a), _b = __float_as_uint(b); \
    asm("mov.b64 %0, {%1, %2};" : "=l"(d) : "r"(_a), "r"(_b)); } while (0)
#define FMA2(a, w, x)  asm("fma.rn.f32x2 %0, %1, %2, %0;" : "+l"(a) : "l"(w), "l"(x))
#define MUL2(d, a, b)  asm("mul.rn.f32x2 %0, %1, %2;" : "=l"(d) : "l"(a), "l"(b))
#define ADD2(d, a, b)  asm("add.rn.f32x2 %0, %1, %2;" : "=l"(d) : "l"(a), "l"(b))

__device__ __forceinline__ float tanh_fast(float x)
{
    float t;
    asm("tanh.approx.f32 %0, %1;" : "=f"(t) : "f"(x));
    return t;
}
__device__ __forceinline__ float sigmoid_fast(float x)
{
    return 0.5f * tanh_fast(0.5f * x) + 0.5f;
}

// -------- scratch --------
__device__ float g_S0[(size_t)N_NODES * HDIM];
__device__ float g_S1[(size_t)N_NODES * HDIM];
__device__ float g_c0[N_NODES];
__device__ float g_c1[N_NODES];
__device__ int   g_cnt[2 * N_NODES];
__device__ int   g_slots[(size_t)2 * N_NODES * PAD];
__device__ int   g_et_is_i32;
__device__ int   g_ovf_n;
__device__ int2  g_ovf[OVF_CAP];

// =====================================================================
__global__ void detect_et_kernel(const unsigned char* __restrict__ et, int E)
{
    __shared__ int cnt;
    if (threadIdx.x == 0) { cnt = 0; g_ovf_n = 0; }
    __syncthreads();
    int K = 4096 < E ? 4096 : E;
    int local = 0;
    for (int i = threadIdx.x; i < K; i += blockDim.x)
        local += (et[i] != 0);
    atomicAdd(&cnt, local);
    __syncthreads();
    if (threadIdx.x == 0)
        g_et_is_i32 = (cnt < K / 4) ? 1 : 0;
}

// =====================================================================
__global__ void __launch_bounds__(256) place_kernel(
    const int*   __restrict__ src,
    const int*   __restrict__ dst,
    const void*  __restrict__ et,
    int E)
{
    int e = blockIdx.x * blockDim.x + threadIdx.x;
    if (e >= E) return;

    bool t;
    if (g_et_is_i32) t = __ldg((const int*)et + e) != 0;
    else             t = __ldg((const unsigned char*)et + e) != 0;
    int ti = t ? 0 : 1;

    int d = __ldg(dst + e);
    int s = __ldg(src + e);
    int seg = d * 2 + ti;
    int slot = atomicAdd(&g_cnt[seg], 1);
    if (slot < PAD) {
        g_slots[(size_t)seg * PAD + slot] = s;
    } else {
        int w = atomicAdd(&g_ovf_n, 1);
        if (w < OVF_CAP) g_ovf[w] = make_int2(seg, s);
    }
}

// =====================================================================
// Segment sum: plain store (no memset of S needed; overflow handled after).
__global__ void __launch_bounds__(256) segsum_kernel(
    const float* __restrict__ feat, int Nn)
{
    int gtid = blockIdx.x * blockDim.x + threadIdx.x;
    int grp = gtid >> 4;
    int l   = gtid & 15;
    if (grp >= 2 * Nn) return;
    int d  = grp >> 1;
    int ti = grp & 1;

    int cnt = g_cnt[grp];
    int m = cnt < PAD ? cnt : PAD;
    const int* sl = g_slots + (size_t)grp * PAD;
    const float4* F = (const float4*)feat;

    float4 acc = make_float4(0.f, 0.f, 0.f, 0.f);
    int i = 0;
    for (; i + 4 <= m; i += 4) {
        int4 s4 = *(const int4*)(sl + i);
        float4 a = __ldg(F + (size_t)s4.x * 16 + l);
        float4 b = __ldg(F + (size_t)s4.y * 16 + l);
        float4 c = __ldg(F + (size_t)s4.z * 16 + l);
        float4 e = __ldg(F + (size_t)s4.w * 16 + l);
        acc.x += (a.x + b.x) + (c.x + e.x);
        acc.y += (a.y + b.y) + (c.y + e.y);
        acc.z += (a.z + b.z) + (c.z + e.z);
        acc.w += (a.w + b.w) + (c.w + e.w);
    }
    for (; i < m; i++) {
        int s = sl[i];
        float4 a = __ldg(F + (size_t)s * 16 + l);
        acc.x += a.x; acc.y += a.y; acc.z += a.z; acc.w += a.w;
    }

    float* S = ti ? g_S1 : g_S0;
    ((float4*)(S + (size_t)d * HDIM))[l] = acc;

    if (l == 0) (ti ? g_c1 : g_c0)[d] = (float)cnt;
}

// =====================================================================
// Overflow fixup (normally 0 iterations): runs AFTER segsum's stores.
__global__ void ovf_fix_kernel(const float* __restrict__ feat)
{
    int m = g_ovf_n;
    if (m > OVF_CAP) m = OVF_CAP;
    int eidx = threadIdx.x >> 4, l = threadIdx.x & 15;
    for (int i = eidx; i < m; i += 16) {
        int2 ov = g_ovf[i];
        float* S = (ov.x & 1) ? g_S1 : g_S0;
        int d = ov.x >> 1;
        float4 v = __ldg((const float4*)(feat + (size_t)ov.y * HDIM) + l);
        atomicAdd((float4*)(S + (size_t)d * HDIM) + l, v);
    }
}

// =====================================================================
// Node kernel v4: 4 threads per node-pair (nodes j and j+64, 16 outputs
// per thread). Weight LDS halved per node; FFMA2 throughout.
// =====================================================================
__device__ __forceinline__ void loadW2(float* sW, const float* __restrict__ A,
                                       const float* __restrict__ B, int row0, int tid)
{
    for (int i = tid; i < 4096; i += TPB) {
        int k = i & 63, m = i >> 6;
        sW[k * WSTR + m]              = A[(row0 + m) * 64 + k];
        sW[64 * WSTR + k * WSTR + m]  = B[(row0 + m) * 64 + k];
    }
}

__global__ void __launch_bounds__(TPB, 2) node_kernel(
    const float* __restrict__ feat,
    const float* __restrict__ W0,  const float* __restrict__ b0,
    const float* __restrict__ W1,  const float* __restrict__ b1,
    const float* __restrict__ Wih, const float* __restrict__ Whh,
    const float* __restrict__ bih, const float* __restrict__ bhh,
    const float* __restrict__ Wout,const float* __restrict__ bout,
    float* __restrict__ out, int Nn)
{
    extern __shared__ float smem[];
    float* sF = smem;                    // 128*65 = 8320
    float* sX = smem + 8320;             // 8320
    float* sW = smem + 16640;            // 2*64*68 = 8704
    float* sB = smem + 25344;            // 528

    const int tid   = threadIdx.x;
    const int j     = tid & 63;          // node-pair index
    const int oq    = tid >> 6;          // output quarter 0..3 (warp-uniform)
    const int mbase = oq * 16;
    const int n0    = blockIdx.x * NPB;
    const int nA    = n0 + j;
    const int nB    = n0 + j + 64;
    const int row0  = j * 65;
    const int row1  = (j + 64) * 65;

    // biases: [0:64) b0 | [64:128) b1 | [128:320) bih | [320:512) bhh | [512:528) bout
    for (int i = tid; i < 528; i += TPB) {
        float v;
        if (i < 64)       v = b0[i];
        else if (i < 128) v = b1[i - 64];
        else if (i < 320) v = bih[i - 128];
        else if (i < 512) v = bhh[i - 320];
        else              v = bout[i - 512];
        sB[i] = v;
    }
    // stage feat + S0 (float4 LDG, scalar STS due to stride-65)
    {
        const float4 z4 = make_float4(0.f, 0.f, 0.f, 0.f);
        const float4* f4 = (const float4*)feat;
        const float4* s04 = (const float4*)g_S0;
        #pragma unroll
        for (int ii = 0; ii < 8; ii++) {
            int i = tid + ii * TPB;
            int r = i >> 4, c4 = i & 15;
            int nn = n0 + r;
            float4 vf = (nn < Nn) ? __ldg(f4 + (size_t)nn * 16 + c4) : z4;
            float4 vs = (nn < Nn) ? __ldg(s04 + (size_t)nn * 16 + c4) : z4;
            float* df = sF + r * 65 + c4 * 4;
            float* dx = sX + r * 65 + c4 * 4;
            df[0] = vf.x; df[1] = vf.y; df[2] = vf.z; df[3] = vf.w;
            dx[0] = vs.x; dx[1] = vs.y; dx[2] = vs.z; dx[3] = vs.w;
        }
    }
    loadW2(sW, W0, W1, 0, tid);

    // prefetch S1 tile into registers (hidden behind agg pass 1)
    float4 s1pre[8];
    {
        const float4 z4 = make_float4(0.f, 0.f, 0.f, 0.f);
        const float4* s14 = (const float4*)g_S1;
        #pragma unroll
        for (int ii = 0; ii < 8; ii++) {
            int i = tid + ii * TPB;
            int r = i >> 4, c4 = i & 15;
            int nn = n0 + r;
            s1pre[ii] = (nn < Nn) ? __ldg(s14 + (size_t)nn * 16 + c4) : z4;
        }
    }
    __syncthreads();

    const ull* pbB = (const ull*)(sB + mbase);  // reused base for bias slices

    // ---- agg: acc[0..7] node A, acc[8..15] node B ----
    ull acc[16];
    {
        float c0a = (nA < Nn) ? g_c0[nA] : 0.f;
        float c1a = (nA < Nn) ? g_c1[nA] : 0.f;
        float c0b = (nB < Nn) ? g_c0[nB] : 0.f;
        float c1b = (nB < Nn) ? g_c1[nB] : 0.f;
        ull c0a2, c1a2, c0b2, c1b2;
        PK2(c0a2, c0a); PK2(c1a2, c1a); PK2(c0b2, c0b); PK2(c1b2, c1b);
        const ull* pb0 = (const ull*)(sB + mbase);
        const ull* pb1 = (const ull*)(sB + 64 + mbase);
        #pragma unroll
        for (int q = 0; q < 8; q++) {
            MUL2(acc[q], c0a2, pb0[q]);     FMA2(acc[q], c1a2, pb1[q]);
            MUL2(acc[8+q], c0b2, pb0[q]);   FMA2(acc[8+q], c1b2, pb1[q]);
        }
    }
    #pragma unroll 4
    for (int k = 0; k < 64; k++) {
        ull x0, x1;
        PK2(x0, sX[row0 + k]); PK2(x1, sX[row1 + k]);
        const ulonglong2* wa = (const ulonglong2*)(sW + k * WSTR + mbase);
        #pragma unroll
        for (int q = 0; q < 4; q++) {
            ulonglong2 a = wa[q];
            FMA2(acc[2*q],    a.x, x0); FMA2(acc[2*q+1],   a.y, x0);
            FMA2(acc[8+2*q],  a.x, x1); FMA2(acc[8+2*q+1], a.y, x1);
        }
    }
    __syncthreads();
    // write prefetched S1 into sX
    #pragma unroll
    for (int ii = 0; ii < 8; ii++) {
        int i = tid + ii * TPB;
        int r = i >> 4, c4 = i & 15;
        float* dx = sX + r * 65 + c4 * 4;
        dx[0] = s1pre[ii].x; dx[1] = s1pre[ii].y;
        dx[2] = s1pre[ii].z; dx[3] = s1pre[ii].w;
    }
    __syncthreads();
    #pragma unroll 4
    for (int k = 0; k < 64; k++) {
        ull x0, x1;
        PK2(x0, sX[row0 + k]); PK2(x1, sX[row1 + k]);
        const ulonglong2* wa = (const ulonglong2*)(sW + 64 * WSTR + k * WSTR + mbase);
        #pragma unroll
        for (int q = 0; q < 4; q++) {
            ulonglong2 a = wa[q];
            FMA2(acc[2*q],    a.x, x0); FMA2(acc[2*q+1],   a.y, x0);
            FMA2(acc[8+2*q],  a.x, x1); FMA2(acc[8+2*q+1], a.y, x1);
        }
    }
    __syncthreads();
    // park agg (own cells)
    #pragma unroll
    for (int q = 0; q < 8; q++) {
        float lo, hi;
        UPK2(lo, hi, acc[q]);
        sX[row0 + mbase + 2*q] = lo; sX[row0 + mbase + 2*q + 1] = hi;
        UPK2(lo, hi, acc[8+q]);
        sX[row1 + mbase + 2*q] = lo; sX[row1 + mbase + 2*q + 1] = hi;
    }
    loadW2(sW, Wih, Whh, 0, tid);
    __syncthreads();

    // ---- r gate ----
    ull rg[16];
    {
        const ull* pbi = (const ull*)(sB + 128 + mbase);
        const ull* pbh = (const ull*)(sB + 320 + mbase);
        #pragma unroll
        for (int q = 0; q < 8; q++) { ADD2(rg[q], pbi[q], pbh[q]); rg[8+q] = rg[q]; }
    }
    #pragma unroll 4
    for (int k = 0; k < 64; k++) {
        ull x0, x1, f0, f1;
        PK2(x0, sX[row0 + k]); PK2(x1, sX[row1 + k]);
        PK2(f0, sF[row0 + k]); PK2(f1, sF[row1 + k]);
        const ulonglong2* wa = (const ulonglong2*)(sW + k * WSTR + mbase);
        const ulonglong2* wb = (const ulonglong2*)(sW + 64 * WSTR + k * WSTR + mbase);
        #pragma unroll
        for (int q = 0; q < 4; q++) {
            ulonglong2 a = wa[q], b = wb[q];
            FMA2(rg[2*q],    a.x, x0); FMA2(rg[2*q+1],   a.y, x0);
            FMA2(rg[2*q],    b.x, f0); FMA2(rg[2*q+1],   b.y, f0);
            FMA2(rg[8+2*q],  a.x, x1); FMA2(rg[8+2*q+1], a.y, x1);
            FMA2(rg[8+2*q],  b.x, f1); FMA2(rg[8+2*q+1], b.y, f1);
        }
    }
    #pragma unroll
    for (int q = 0; q < 16; q++) {
        float lo, hi; UPK2(lo, hi, rg[q]);
        lo = sigmoid_fast(lo); hi = sigmoid_fast(hi);
        RPK2(rg[q], lo, hi);
    }

    // ---- n gate: nv = i_n + r * h_n ----
    __syncthreads();
    loadW2(sW, Wih, Whh, 128, tid);
    __syncthreads();
    ull nv[16];
    {
        const ull* pbi = (const ull*)(sB + 256 + mbase);
        const ull* pbh = (const ull*)(sB + 448 + mbase);
        #pragma unroll
        for (int q = 0; q < 8; q++) {
            nv[q] = pbi[q];   FMA2(nv[q],   rg[q],   pbh[q]);
            nv[8+q] = pbi[q]; FMA2(nv[8+q], rg[8+q], pbh[q]);
        }
    }
    #pragma unroll 4
    for (int k = 0; k < 64; k++) {
        ull x0, x1, f0, f1;
        PK2(x0, sX[row0 + k]); PK2(x1, sX[row1 + k]);
        PK2(f0, sF[row0 + k]); PK2(f1, sF[row1 + k]);
        const ulonglong2* wa = (const ulonglong2*)(sW + k * WSTR + mbase);
        const ulonglong2* wb = (const ulonglong2*)(sW + 64 * WSTR + k * WSTR + mbase);
        #pragma unroll
        for (int q = 0; q < 4; q++) {
            ulonglong2 a = wa[q], b = wb[q];
            ull t0, t1;
            FMA2(nv[2*q],   a.x, x0); FMA2(nv[2*q+1],   a.y, x0);
            MUL2(t0, b.x, f0);        MUL2(t1, b.y, f0);
            FMA2(nv[2*q],   t0, rg[2*q]); FMA2(nv[2*q+1], t1, rg[2*q+1]);
            FMA2(nv[8+2*q], a.x, x1); FMA2(nv[8+2*q+1], a.y, x1);
            MUL2(t0, b.x, f1);        MUL2(t1, b.y, f1);
            FMA2(nv[8+2*q], t0, rg[8+2*q]); FMA2(nv[8+2*q+1], t1, rg[8+2*q+1]);
        }
    }
    #pragma unroll
    for (int q = 0; q < 16; q++) {
        float lo, hi; UPK2(lo, hi, nv[q]);
        lo = tanh_fast(lo); hi = tanh_fast(hi);
        RPK2(nv[q], lo, hi);
    }

    // ---- z gate ----
    __syncthreads();
    loadW2(sW, Wih, Whh, 64, tid);
    __syncthreads();
    ull zg[16];
    {
        const ull* pbi = (const ull*)(sB + 192 + mbase);
        const ull* pbh = (const ull*)(sB + 384 + mbase);
        #pragma unroll
        for (int q = 0; q < 8; q++) { ADD2(zg[q], pbi[q], pbh[q]); zg[8+q] = zg[q]; }
    }
    #pragma unroll 4
    for (int k = 0; k < 64; k++) {
        ull x0, x1, f0, f1;
        PK2(x0, sX[row0 + k]); PK2(x1, sX[row1 + k]);
        PK2(f0, sF[row0 + k]); PK2(f1, sF[row1 + k]);
        const ulonglong2* wa = (const ulonglong2*)(sW + k * WSTR + mbase);
        const ulonglong2* wb = (const ulonglong2*)(sW + 64 * WSTR + k * WSTR + mbase);
        #pragma unroll
        for (int q = 0; q < 4; q++) {
            ulonglong2 a = wa[q], b = wb[q];
            FMA2(zg[2*q],    a.x, x0); FMA2(zg[2*q+1],   a.y, x0);
            FMA2(zg[2*q],    b.x, f0); FMA2(zg[2*q+1],   b.y, f0);
            FMA2(zg[8+2*q],  a.x, x1); FMA2(zg[8+2*q+1], a.y, x1);
            FMA2(zg[8+2*q],  b.x, f1); FMA2(zg[8+2*q+1], b.y, f1);
        }
    }
    __syncthreads();   // all gate reads of sX done
    // h = n + z*(f - n); park into sX
    #pragma unroll
    for (int q = 0; q < 8; q++) {
        float zlo, zhi, nlo, nhi;
        UPK2(zlo, zhi, zg[q]);   UPK2(nlo, nhi, nv[q]);
        zlo = sigmoid_fast(zlo); zhi = sigmoid_fast(zhi);
        sX[row0 + mbase + 2*q]     = nlo + zlo * (sF[row0 + mbase + 2*q]     - nlo);
        sX[row0 + mbase + 2*q + 1] = nhi + zhi * (sF[row0 + mbase + 2*q + 1] - nhi);
        UPK2(zlo, zhi, zg[8+q]); UPK2(nlo, nhi, nv[8+q]);
        zlo = sigmoid_fast(zlo); zhi = sigmoid_fast(zhi);
        sX[row1 + mbase + 2*q]     = nlo + zlo * (sF[row1 + mbase + 2*q]     - nlo);
        sX[row1 + mbase + 2*q + 1] = nhi + zhi * (sF[row1 + mbase + 2*q + 1] - nhi);
    }
    // stage classifier weights
    for (int i = tid; i < 1024; i += TPB) {
        int k = i & 63, c = i >> 6;
        sW[k * 16 + c] = Wout[c * 64 + k];
    }
    __syncthreads();

    // ---- classifier: 2 nodes x 4 classes per thread ----
    float oA[4], oB[4];
    #pragma unroll
    for (int c = 0; c < 4; c++) { oA[c] = sB[512 + oq * 4 + c]; oB[c] = oA[c]; }
    #pragma unroll 4
    for (int k = 0; k < 64; k++) {
        float h0 = sX[row0 + k], h1 = sX[row1 + k];
        float4 w = *(const float4*)(sW + k * 16 + oq * 4);
        oA[0] += h0 * w.x; oA[1] += h0 * w.y; oA[2] += h0 * w.z; oA[3] += h0 * w.w;
        oB[0] += h1 * w.x; oB[1] += h1 * w.y; oB[2] += h1 * w.z; oB[3] += h1 * w.w;
    }
    if (nA < Nn)
        *(float4*)(out + (size_t)nA * 16 + oq * 4) = make_float4(oA[0], oA[1], oA[2], oA[3]);
    if (nB < Nn)
        *(float4*)(out + (size_t)nB * 16 + oq * 4) = make_float4(oB[0], oB[1], oB[2], oB[3]);
}

// =====================================================================
extern "C" void kernel_launch(void* const* d_in, const int* in_sizes, int n_in,
                              void* d_out, int out_size)
{
    const float* feat = (const float*)d_in[0];
    const int*   src  = (const int*)d_in[1];
    const int*   dst  = (const int*)d_in[2];
    const void*  et   = d_in[3];
    const float* W0   = (const float*)d_in[4];
    const float* b0   = (const float*)d_in[5];
    const float* W1   = (const float*)d_in[6];
    const float* b1   = (const float*)d_in[7];
    const float* Wih  = (const float*)d_in[8];
    const float* Whh  = (const float*)d_in[9];
    const float* bih  = (const float*)d_in[10];
    const float* bhh  = (const float*)d_in[11];
    const float* Wout = (const float*)d_in[12];
    const float* bout = (const float*)d_in[13];
    float* out = (float*)d_out;

    const int E  = in_sizes[1];
    const int Nn = in_sizes[0] / HDIM;

    void* p;
    cudaGetSymbolAddress(&p, g_cnt);
    cudaMemsetAsync(p, 0, sizeof(int) * 2 * N_NODES);

    detect_et_kernel<<<1, 256>>>((const unsigned char*)et, E);

    place_kernel<<<(E + 255) / 256, 256>>>(src, dst, et, E);

    {
        long long tot = (long long)(2 * Nn) * 16;
        int blocks = (int)((tot + 255) / 256);
        segsum_kernel<<<blocks, 256>>>(feat, Nn);
    }
    ovf_fix_kernel<<<1, 256>>>(feat);
    {
        size_t smem = (size_t)(8320 * 2 + 8704 + 528) * sizeof(float); // 103488 B
        cudaFuncSetAttribute(node_kernel, cudaFuncAttributeMaxDynamicSharedMemorySize, (int)smem);
        int nb = (Nn + NPB - 1) / NPB;
        node_kernel<<<nb, TPB, smem>>>(feat, W0, b0, W1, b1, Wih, Whh,
                                       bih, bhh, Wout, bout, out, Nn);
    }
}